// round 12
// baseline (speedup 1.0000x reference)
#include <cuda_runtime.h>
#include <cuda_fp16.h>
#include <cstdint>

// ============================================================================
// LSTM cell, two kernels:
//  1) convert: fp32 -> fp16 into __device__ globals (combined [x|h], W per gate)
//  2) GEMM via mma.sync fp16 m16n8k16, cp.async mainloop.
// R12: R11's mbarrier pipeline with the deadlock fix — use
//      cp.async.mbarrier.arrive.NOINC (the non-noinc form self-balances the
//      expected count and the barrier never flips).
// CTA: M=64, per-gate N=64 (4 gates), 8 warps = 2(M) x 4(gate), warp 32x64.
// BK=32, 64 iters, 4 smem stages, 2 CTAs/SM.
// ============================================================================

#define BATCH     8192
#define SA_B      80                          // A smem row stride bytes
#define SB_B      144                         // B smem row stride bytes
#define A_BYTES   (64 * SA_B)                 // 5120
#define BG_BYTES  (32 * SB_B)                 // 4608 per gate
#define STAGE_BYTES (A_BYTES + 4 * BG_BYTES)  // 23552
#define NSTAGES   4
#define SS        260                         // epilogue staging stride (floats)
#define MB_OFF    (NSTAGES * STAGE_BYTES)     // 94208: mbarriers after stages
#define SMEM_BYTES (MB_OFF + 128)             // 94336/CTA; 2 CTAs/SM fits

__device__ static __half A_h[(size_t)BATCH * 2048];      // combined [x|h], 32MB
__device__ static __half W_h[4][(size_t)2048 * 1024];    // per-gate weights, 16MB

// ---------------------------------------------------------------- convert ---
__global__ void __launch_bounds__(256) convert_kernel(
    const float* __restrict__ x, const float* __restrict__ h,
    const float* __restrict__ Wf, const float* __restrict__ Wi,
    const float* __restrict__ Wc, const float* __restrict__ Wo)
{
    const size_t NA = (size_t)BATCH * 2048 / 4;
    const size_t NW = (size_t)2048 * 1024 / 4;
    const size_t total = NA + 4 * NW;
    const size_t stride = (size_t)gridDim.x * blockDim.x;

    for (size_t i = (size_t)blockIdx.x * blockDim.x + threadIdx.x;
         i < total; i += stride) {
        float4 v;
        __half* dst;
        if (i < NA) {
            size_t m = i >> 9;
            size_t k = (i & 511) * 4;
            const float* src = (k < 1024) ? (x + m * 1024 + k)
                                          : (h + m * 1024 + (k - 1024));
            v = *reinterpret_cast<const float4*>(src);
            dst = &A_h[i * 4];
        } else {
            size_t j = i - NA;
            size_t g = j / NW;
            size_t r = j - g * NW;
            const float* Wg = (g == 0) ? Wf : (g == 1) ? Wi : (g == 2) ? Wc : Wo;
            v = *reinterpret_cast<const float4*>(Wg + r * 4);
            dst = &W_h[g][r * 4];
        }
        __half2 lo = __floats2half2_rn(v.x, v.y);
        __half2 hi = __floats2half2_rn(v.z, v.w);
        uint2 out = { *reinterpret_cast<uint32_t*>(&lo), *reinterpret_cast<uint32_t*>(&hi) };
        *reinterpret_cast<uint2*>(dst) = out;
    }
}

// ------------------------------------------------------------------ GEMM ----
__device__ __forceinline__ uint32_t s2u(const void* p) {
    uint32_t a;
    asm("{ .reg .u64 t; cvta.to.shared.u64 t, %1; cvt.u32.u64 %0, t; }"
        : "=r"(a) : "l"(p));
    return a;
}
__device__ __forceinline__ void cp16(uint32_t dst, const __half* src) {
    asm volatile("cp.async.cg.shared.global [%0], [%1], 16;" :: "r"(dst), "l"(src));
}
__device__ __forceinline__ void mbar_init(uint32_t a, uint32_t c) {
    asm volatile("mbarrier.init.shared.b64 [%0], %1;" :: "r"(a), "r"(c) : "memory");
}
__device__ __forceinline__ void mbar_arrive(uint32_t a) {
    asm volatile("mbarrier.arrive.shared.b64 _, [%0];" :: "r"(a) : "memory");
}
__device__ __forceinline__ void cp_arrive_noinc(uint32_t a) {
    asm volatile("cp.async.mbarrier.arrive.noinc.shared.b64 [%0];" :: "r"(a) : "memory");
}
__device__ __forceinline__ void mbar_wait(uint32_t a, uint32_t ph) {
    asm volatile(
        "{\n\t.reg .pred P;\n\t"
        "WL%=:\n\t"
        "mbarrier.try_wait.parity.acquire.cta.shared::cta.b64 P, [%0], %1, 0x989680;\n\t"
        "@P bra WD%=;\n\t"
        "bra WL%=;\n\t"
        "WD%=:\n\t}"
        :: "r"(a), "r"(ph) : "memory");
}

__device__ __forceinline__ void ldsm4(uint32_t* r, uint32_t addr) {
    asm volatile("ldmatrix.sync.aligned.m8n8.x4.shared.b16 {%0,%1,%2,%3}, [%4];"
                 : "=r"(r[0]), "=r"(r[1]), "=r"(r[2]), "=r"(r[3]) : "r"(addr));
}
__device__ __forceinline__ void ldsm4t(uint32_t* r, uint32_t addr) {
    asm volatile("ldmatrix.sync.aligned.m8n8.x4.trans.shared.b16 {%0,%1,%2,%3}, [%4];"
                 : "=r"(r[0]), "=r"(r[1]), "=r"(r[2]), "=r"(r[3]) : "r"(addr));
}
__device__ __forceinline__ void mma16(float* d, const uint32_t* a, const uint32_t* b) {
    asm volatile(
        "mma.sync.aligned.m16n8k16.row.col.f32.f16.f16.f32 "
        "{%0,%1,%2,%3}, {%4,%5,%6,%7}, {%8,%9}, {%0,%1,%2,%3};"
        : "+f"(d[0]), "+f"(d[1]), "+f"(d[2]), "+f"(d[3])
        : "r"(a[0]), "r"(a[1]), "r"(a[2]), "r"(a[3]), "r"(b[0]), "r"(b[1]));
}
__device__ __forceinline__ float sigf(float v) {
    return __fdividef(1.0f, 1.0f + __expf(-v));
}
__device__ __forceinline__ float tanhf_e(float v) {
    float ax = fabsf(v);
    float e = __expf(-2.0f * ax);
    float t = __fdividef(1.0f - e, 1.0f + e);
    return copysignf(t, v);
}

// cp.async one BK=32 stage: A 256 chunks (1/thread), B 1024 chunks (4/thread)
__device__ __forceinline__ void load_stage(int T, int tid, uint32_t sb, int m0, int n0)
{
    const uint32_t Ab = sb + (T % NSTAGES) * STAGE_BYTES;
    const int k0 = T * 32;
    {
        int row = tid >> 2, col = tid & 3;
        cp16(Ab + row * SA_B + col * 16,
             &A_h[(size_t)(m0 + row) * 2048 + k0 + col * 8]);
    }
    const uint32_t Bb = Ab + A_BYTES;
    #pragma unroll
    for (int c = 0; c < 4; c++) {          // gate == c
        int kr = tid >> 3, col = tid & 7;
        cp16(Bb + c * BG_BYTES + kr * SB_B + col * 16,
             &W_h[c][(size_t)(k0 + kr) * 1024 + n0 + col * 8]);
    }
}

__global__ void __launch_bounds__(256, 2)
lstm_mma(const float* __restrict__ cellp,
         const float* __restrict__ bf, const float* __restrict__ bi,
         const float* __restrict__ bc, const float* __restrict__ bo,
         float* __restrict__ outh, float* __restrict__ outc)
{
    extern __shared__ float sm[];
    const uint32_t sb = s2u(sm);
    const uint32_t mb = sb + MB_OFF;      // full[s]=mb+16s, empty[s]=mb+16s+8

    const int tid  = threadIdx.x;
    const int lane = tid & 31;
    const int wid  = tid >> 5;
    const int g    = wid & 3;             // gate handled by this warp
    const int wm   = wid >> 2;            // M half within CTA (0/1)
    const int m0   = blockIdx.x * 64;
    const int n0   = blockIdx.y * 64;

    const int l15  = lane & 15;
    const int ahi  = (lane >> 4) * 16;
    const int bhi  = (lane >> 4) * 8;

    if (tid == 0) {
        #pragma unroll
        for (int s = 0; s < NSTAGES; s++) {
            mbar_init(mb + s * 16, 256);      // full: one noinc-arrive per thread
            mbar_init(mb + s * 16 + 8, 8);    // empty: one arrive per warp
        }
    }
    __syncthreads();

    float acc[2][8][4];
    #pragma unroll
    for (int mt = 0; mt < 2; mt++)
        #pragma unroll
        for (int nt = 0; nt < 8; nt++)
            #pragma unroll
            for (int j = 0; j < 4; j++) acc[mt][nt][j] = 0.0f;

    // prologue: produce stages 0 and 1 (no empty-wait needed, T < NSTAGES)
    load_stage(0, tid, sb, m0, n0); cp_arrive_noinc(mb + 0 * 16);
    load_stage(1, tid, sb, m0, n0); cp_arrive_noinc(mb + 1 * 16);

    for (int t = 0; t < 64; t++) {
        // ---- producer: stage T = t+2 ----
        const int T = t + 2;
        if (T < 64) {
            const int sT = T & (NSTAGES - 1);
            if (T >= NSTAGES)
                mbar_wait(mb + sT * 16 + 8, ((T >> 2) - 1) & 1);
            load_stage(T, tid, sb, m0, n0);
            cp_arrive_noinc(mb + sT * 16);
        }

        // ---- consumer: stage t ----
        const int s = t & (NSTAGES - 1);
        mbar_wait(mb + s * 16, (t >> 2) & 1);

        const uint32_t Ab = sb + s * STAGE_BYTES;
        const uint32_t Bg = Ab + A_BYTES + g * BG_BYTES;

        #pragma unroll
        for (int ks = 0; ks < 2; ks++) {
            uint32_t a[2][4];
            #pragma unroll
            for (int mt = 0; mt < 2; mt++)
                ldsm4(a[mt], Ab + (uint32_t)(wm * 32 + mt * 16 + l15) * SA_B
                               + (uint32_t)(ks * 32 + ahi));
            uint32_t b[8][2];
            #pragma unroll
            for (int np = 0; np < 4; np++) {
                uint32_t r[4];
                ldsm4t(r, Bg + (uint32_t)(ks * 16 + l15) * SB_B
                             + (uint32_t)(np * 16 + bhi) * 2);
                b[np * 2][0] = r[0]; b[np * 2][1] = r[1];
                b[np * 2 + 1][0] = r[2]; b[np * 2 + 1][1] = r[3];
            }
            #pragma unroll
            for (int mt = 0; mt < 2; mt++)
                #pragma unroll
                for (int nt = 0; nt < 8; nt++)
                    mma16(acc[mt][nt], a[mt], b[nt]);
        }

        if (lane == 0) mbar_arrive(mb + s * 16 + 8);   // release: reads done
    }
    __syncthreads();       // all warps done; smem reused for staging

    // ---- stage gate values through smem (gates live in different warps) ----
    #pragma unroll
    for (int mt = 0; mt < 2; mt++) {
        #pragma unroll
        for (int nt = 0; nt < 8; nt++) {
            int r0 = wm * 32 + mt * 16 + (lane >> 2);
            int cb = g * 64 + nt * 8 + (lane & 3) * 2;
            *(float2*)&sm[(size_t)r0 * SS + cb]       = make_float2(acc[mt][nt][0], acc[mt][nt][1]);
            *(float2*)&sm[(size_t)(r0 + 8) * SS + cb] = make_float2(acc[mt][nt][2], acc[mt][nt][3]);
        }
    }
    __syncthreads();

    // ---- fused LSTM combine + store (64 x 64 tile, 16 elems/thread) ----
    const int nl   = tid & 63;
    const int mseg = tid >> 6;            // 0..3
    const int n    = n0 + nl;
    const float Bf = __ldg(bf + n);
    const float Bi = __ldg(bi + n);
    const float Bc = __ldg(bc + n);
    const float Bo = __ldg(bo + n);

    #pragma unroll 4
    for (int r = 0; r < 16; r++) {
        int m = r * 4 + mseg;
        const float* row = &sm[(size_t)m * SS];
        float gf = row[nl]       + Bf;
        float gi = row[64 + nl]  + Bi;
        float gc = row[128 + nl] + Bc;
        float go = row[192 + nl] + Bo;

        float F  = sigf(gf);
        float I  = sigf(gi);
        float O  = sigf(go);
        float CD = tanhf_e(gc);

        size_t gidx = (size_t)(m0 + m) * 1024 + n;
        float cold = __ldg(cellp + gidx);
        float nc = fmaf(F, cold, I * CD);
        float nh = O * tanhf_e(nc);
        outh[gidx] = nh;
        outc[gidx] = nc;
    }
}

extern "C" void kernel_launch(void* const* d_in, const int* in_sizes, int n_in,
                              void* d_out, int out_size)
{
    const float* x    = (const float*)d_in[0];   // [B, 1024]
    const float* h    = (const float*)d_in[1];   // [B, 1024]
    const float* cell = (const float*)d_in[2];   // [B, 1024]
    const float* Wf   = (const float*)d_in[3];   // [2048, 1024]
    const float* bf   = (const float*)d_in[4];
    const float* Wi   = (const float*)d_in[5];
    const float* bi   = (const float*)d_in[6];
    const float* Wc   = (const float*)d_in[7];
    const float* bc   = (const float*)d_in[8];
    const float* Wo   = (const float*)d_in[9];
    const float* bo   = (const float*)d_in[10];

    const int B = in_sizes[0] / 1024;            // 8192

    static bool attr_set = false;
    if (!attr_set) {
        cudaFuncSetAttribute(lstm_mma, cudaFuncAttributeMaxDynamicSharedMemorySize,
                             SMEM_BYTES);
        attr_set = true;
    }

    convert_kernel<<<2048, 256>>>(x, h, Wf, Wi, Wc, Wo);

    float* outh = (float*)d_out;
    float* outc = (float*)d_out + (size_t)B * 1024;

    dim3 grid(B / 64, 16);
    lstm_mma<<<grid, 256, SMEM_BYTES>>>(cell, bf, bi, bc, bo, outh, outc);
}

// round 13
// speedup vs baseline: 1.4397x; 1.4397x over previous
#include <cuda_runtime.h>
#include <cuda_fp16.h>
#include <cstdint>

// ============================================================================
// LSTM cell, two kernels:
//  1) convert: fp32 -> fp16 into __device__ globals (combined [x|h], W per gate)
//  2) GEMM via mma.sync fp16 m16n8k16, cp.async mainloop.
// R13: revert to __syncthreads (mbarrier TRYWAIT cost > convoy cost, measured).
//      CTA = 128 threads / 4 warps, one warp per gate, warp tile 64x64
//      (acc 128 regs) -> 2x fewer LDSM per HMMA than R10, cheap 4-warp barrier,
//      fragment double-buffering, 2 CTAs/SM for cross-CTA bubble coverage.
// BK=32, 64 iters, 4 smem stages.
// ============================================================================

#define BATCH     8192
#define SA_B      80                          // A smem row stride bytes
#define SB_B      144                         // B smem row stride bytes
#define A_BYTES   (64 * SA_B)                 // 5120
#define BG_BYTES  (32 * SB_B)                 // 4608 per gate
#define STAGE_BYTES (A_BYTES + 4 * BG_BYTES)  // 23552
#define NSTAGES   4
#define SS        260                         // epilogue staging stride (floats)
#define SMEM_BYTES (NSTAGES * STAGE_BYTES)    // 94208/CTA; 2 CTAs/SM fits

__device__ static __half A_h[(size_t)BATCH * 2048];      // combined [x|h], 32MB
__device__ static __half W_h[4][(size_t)2048 * 1024];    // per-gate weights, 16MB

// ---------------------------------------------------------------- convert ---
__global__ void __launch_bounds__(256) convert_kernel(
    const float* __restrict__ x, const float* __restrict__ h,
    const float* __restrict__ Wf, const float* __restrict__ Wi,
    const float* __restrict__ Wc, const float* __restrict__ Wo)
{
    const size_t NA = (size_t)BATCH * 2048 / 4;
    const size_t NW = (size_t)2048 * 1024 / 4;
    const size_t total = NA + 4 * NW;
    const size_t stride = (size_t)gridDim.x * blockDim.x;

    for (size_t i = (size_t)blockIdx.x * blockDim.x + threadIdx.x;
         i < total; i += stride) {
        float4 v;
        __half* dst;
        if (i < NA) {
            size_t m = i >> 9;
            size_t k = (i & 511) * 4;
            const float* src = (k < 1024) ? (x + m * 1024 + k)
                                          : (h + m * 1024 + (k - 1024));
            v = *reinterpret_cast<const float4*>(src);
            dst = &A_h[i * 4];
        } else {
            size_t j = i - NA;
            size_t g = j / NW;
            size_t r = j - g * NW;
            const float* Wg = (g == 0) ? Wf : (g == 1) ? Wi : (g == 2) ? Wc : Wo;
            v = *reinterpret_cast<const float4*>(Wg + r * 4);
            dst = &W_h[g][r * 4];
        }
        __half2 lo = __floats2half2_rn(v.x, v.y);
        __half2 hi = __floats2half2_rn(v.z, v.w);
        uint2 out = { *reinterpret_cast<uint32_t*>(&lo), *reinterpret_cast<uint32_t*>(&hi) };
        *reinterpret_cast<uint2*>(dst) = out;
    }
}

// ------------------------------------------------------------------ GEMM ----
__device__ __forceinline__ uint32_t s2u(const void* p) {
    uint32_t a;
    asm("{ .reg .u64 t; cvta.to.shared.u64 t, %1; cvt.u32.u64 %0, t; }"
        : "=r"(a) : "l"(p));
    return a;
}
__device__ __forceinline__ void cp16(uint32_t dst, const __half* src) {
    asm volatile("cp.async.cg.shared.global [%0], [%1], 16;" :: "r"(dst), "l"(src));
}
#define CP_COMMIT() asm volatile("cp.async.commit_group;" ::: "memory")
#define CP_WAIT(n)  asm volatile("cp.async.wait_group %0;" :: "n"(n) : "memory")

__device__ __forceinline__ void ldsm4(uint32_t* r, uint32_t addr) {
    asm volatile("ldmatrix.sync.aligned.m8n8.x4.shared.b16 {%0,%1,%2,%3}, [%4];"
                 : "=r"(r[0]), "=r"(r[1]), "=r"(r[2]), "=r"(r[3]) : "r"(addr));
}
__device__ __forceinline__ void ldsm4t(uint32_t* r, uint32_t addr) {
    asm volatile("ldmatrix.sync.aligned.m8n8.x4.trans.shared.b16 {%0,%1,%2,%3}, [%4];"
                 : "=r"(r[0]), "=r"(r[1]), "=r"(r[2]), "=r"(r[3]) : "r"(addr));
}
__device__ __forceinline__ void mma16(float* d, const uint32_t* a, const uint32_t* b) {
    asm volatile(
        "mma.sync.aligned.m16n8k16.row.col.f32.f16.f16.f32 "
        "{%0,%1,%2,%3}, {%4,%5,%6,%7}, {%8,%9}, {%0,%1,%2,%3};"
        : "+f"(d[0]), "+f"(d[1]), "+f"(d[2]), "+f"(d[3])
        : "r"(a[0]), "r"(a[1]), "r"(a[2]), "r"(a[3]), "r"(b[0]), "r"(b[1]));
}
__device__ __forceinline__ float sigf(float v) {
    return __fdividef(1.0f, 1.0f + __expf(-v));
}
__device__ __forceinline__ float tanhf_e(float v) {
    float ax = fabsf(v);
    float e = __expf(-2.0f * ax);
    float t = __fdividef(1.0f - e, 1.0f + e);
    return copysignf(t, v);
}

// cp.async one BK=32 stage, 128 threads:
// A: 256 chunks (2/thread), B: 1024 chunks (8/thread, gate = c>>1)
__device__ __forceinline__ void load_stage(int T, int tid, uint32_t sb, int m0, int n0)
{
    const uint32_t Ab = sb + (T % NSTAGES) * STAGE_BYTES;
    const int k0 = T * 32;
    #pragma unroll
    for (int c = 0; c < 2; c++) {
        int idx = c * 128 + tid;
        int row = idx >> 2, col = idx & 3;
        cp16(Ab + row * SA_B + col * 16,
             &A_h[(size_t)(m0 + row) * 2048 + k0 + col * 8]);
    }
    const uint32_t Bb = Ab + A_BYTES;
    #pragma unroll
    for (int c = 0; c < 8; c++) {
        int g = c >> 1;                    // constant per unrolled c
        int idx = (c & 1) * 128 + tid;     // 0..255 within gate
        int kr = idx >> 3, col = idx & 7;
        cp16(Bb + g * BG_BYTES + kr * SB_B + col * 16,
             &W_h[g][(size_t)(k0 + kr) * 1024 + n0 + col * 8]);
    }
}

__global__ void __launch_bounds__(128, 2)
lstm_mma(const float* __restrict__ cellp,
         const float* __restrict__ bf, const float* __restrict__ bi,
         const float* __restrict__ bc, const float* __restrict__ bo,
         float* __restrict__ outh, float* __restrict__ outc)
{
    extern __shared__ float sm[];
    const uint32_t sb = s2u(sm);

    const int tid  = threadIdx.x;
    const int lane = tid & 31;
    const int g    = tid >> 5;            // warp == gate (0..3)
    const int m0   = blockIdx.x * 64;
    const int n0   = blockIdx.y * 64;

    const int l15  = lane & 15;
    const int ahi  = (lane >> 4) * 16;    // A: 16B k-half select
    const int bhi  = (lane >> 4) * 8;     // B: n-chunk select

    float acc[4][8][4];
    #pragma unroll
    for (int mt = 0; mt < 4; mt++)
        #pragma unroll
        for (int nt = 0; nt < 8; nt++)
            #pragma unroll
            for (int j = 0; j < 4; j++) acc[mt][nt][j] = 0.0f;

    load_stage(0, tid, sb, m0, n0); CP_COMMIT();
    load_stage(1, tid, sb, m0, n0); CP_COMMIT();

    for (int t = 0; t < 64; t++) {
        if (t < 62) {
            load_stage(t + 2, tid, sb, m0, n0);
            CP_COMMIT();
            CP_WAIT(2);
        } else if (t == 62) {
            CP_WAIT(1);
        } else {
            CP_WAIT(0);
        }
        __syncthreads();

        const uint32_t Ab = sb + (t % NSTAGES) * STAGE_BYTES;
        const uint32_t Bg = Ab + A_BYTES + g * BG_BYTES;

        uint32_t afr[2][4][4], bfr[2][8][2];

        // prologue: frags for ks=0
        #pragma unroll
        for (int mt = 0; mt < 4; mt++)
            ldsm4(afr[0][mt], Ab + (uint32_t)(mt * 16 + l15) * SA_B + ahi);
        #pragma unroll
        for (int np = 0; np < 4; np++) {
            uint32_t r[4];
            ldsm4t(r, Bg + (uint32_t)l15 * SB_B + (uint32_t)(np * 16 + bhi) * 2);
            bfr[0][np * 2][0] = r[0]; bfr[0][np * 2][1] = r[1];
            bfr[0][np * 2 + 1][0] = r[2]; bfr[0][np * 2 + 1][1] = r[3];
        }

        #pragma unroll
        for (int ks = 0; ks < 2; ks++) {          // two k16 steps (BK=32)
            const int cur = ks & 1, nxt = cur ^ 1;
            if (ks < 1) {
                #pragma unroll
                for (int mt = 0; mt < 4; mt++)
                    ldsm4(afr[nxt][mt],
                          Ab + (uint32_t)(mt * 16 + l15) * SA_B + (uint32_t)(32 + ahi));
                #pragma unroll
                for (int np = 0; np < 4; np++) {
                    uint32_t r[4];
                    ldsm4t(r, Bg + (uint32_t)(16 + l15) * SB_B
                                 + (uint32_t)(np * 16 + bhi) * 2);
                    bfr[nxt][np * 2][0] = r[0]; bfr[nxt][np * 2][1] = r[1];
                    bfr[nxt][np * 2 + 1][0] = r[2]; bfr[nxt][np * 2 + 1][1] = r[3];
                }
            }
            #pragma unroll
            for (int mt = 0; mt < 4; mt++)
                #pragma unroll
                for (int nt = 0; nt < 8; nt++)
                    mma16(acc[mt][nt], afr[cur][mt], bfr[cur][nt]);
        }
    }
    __syncthreads();       // mainloop done; smem reused for staging

    // ---- stage gate values through smem (gates live in different warps) ----
    #pragma unroll
    for (int mt = 0; mt < 4; mt++) {
        #pragma unroll
        for (int nt = 0; nt < 8; nt++) {
            int r0 = mt * 16 + (lane >> 2);
            int cb = g * 64 + nt * 8 + (lane & 3) * 2;
            *(float2*)&sm[(size_t)r0 * SS + cb]       = make_float2(acc[mt][nt][0], acc[mt][nt][1]);
            *(float2*)&sm[(size_t)(r0 + 8) * SS + cb] = make_float2(acc[mt][nt][2], acc[mt][nt][3]);
        }
    }
    __syncthreads();

    // ---- fused LSTM combine + store (64 x 64 tile, 32 elems/thread) ----
    const int nl   = tid & 63;
    const int mseg = tid >> 6;            // 0..1
    const int n    = n0 + nl;
    const float Bf = __ldg(bf + n);
    const float Bi = __ldg(bi + n);
    const float Bc = __ldg(bc + n);
    const float Bo = __ldg(bo + n);

    #pragma unroll 4
    for (int r = 0; r < 32; r++) {
        int m = r * 2 + mseg;
        const float* row = &sm[(size_t)m * SS];
        float gf = row[nl]       + Bf;
        float gi = row[64 + nl]  + Bi;
        float gc = row[128 + nl] + Bc;
        float go = row[192 + nl] + Bo;

        float F  = sigf(gf);
        float I  = sigf(gi);
        float O  = sigf(go);
        float CD = tanhf_e(gc);

        size_t gidx = (size_t)(m0 + m) * 1024 + n;
        float cold = __ldg(cellp + gidx);
        float nc = fmaf(F, cold, I * CD);
        float nh = O * tanhf_e(nc);
        outh[gidx] = nh;
        outc[gidx] = nc;
    }
}

extern "C" void kernel_launch(void* const* d_in, const int* in_sizes, int n_in,
                              void* d_out, int out_size)
{
    const float* x    = (const float*)d_in[0];   // [B, 1024]
    const float* h    = (const float*)d_in[1];   // [B, 1024]
    const float* cell = (const float*)d_in[2];   // [B, 1024]
    const float* Wf   = (const float*)d_in[3];   // [2048, 1024]
    const float* bf   = (const float*)d_in[4];
    const float* Wi   = (const float*)d_in[5];
    const float* bi   = (const float*)d_in[6];
    const float* Wc   = (const float*)d_in[7];
    const float* bc   = (const float*)d_in[8];
    const float* Wo   = (const float*)d_in[9];
    const float* bo   = (const float*)d_in[10];

    const int B = in_sizes[0] / 1024;            // 8192

    static bool attr_set = false;
    if (!attr_set) {
        cudaFuncSetAttribute(lstm_mma, cudaFuncAttributeMaxDynamicSharedMemorySize,
                             SMEM_BYTES);
        attr_set = true;
    }

    convert_kernel<<<2048, 256>>>(x, h, Wf, Wi, Wc, Wo);

    float* outh = (float*)d_out;
    float* outc = (float*)d_out + (size_t)B * 1024;

    dim3 grid(B / 64, 16);
    lstm_mma<<<grid, 128, SMEM_BYTES>>>(cell, bf, bi, bc, bo, outh, outc);
}

// round 15
// speedup vs baseline: 1.4503x; 1.0073x over previous
#include <cuda_runtime.h>
#include <cuda_fp16.h>
#include <cstdint>

// ============================================================================
// LSTM cell, two kernels:
//  1) convert: fp32 -> fp16 into __device__ globals (combined [x|h], W per gate)
//  2) GEMM via mma.sync fp16 m16n8k16, cp.async mainloop.
// R15: cross-barrier fragment pipelining, FIXED — the __syncthreads moves to
//      mid-iteration (after CP_WAIT, before the cross-stage frag load), so the
//      stage being preloaded is published by ALL threads' copies first.
//      (R14 read stage t+1 before the barrier -> cp.async visibility race.)
// CTA: 128 thr / 4 warps, warp==gate, warp tile 64x64, BK=32, 2 CTAs/SM.
// ============================================================================

#define BATCH     8192
#define SA_B      80                          // A smem row stride bytes
#define SB_B      144                         // B smem row stride bytes
#define A_BYTES   (64 * SA_B)                 // 5120
#define BG_BYTES  (32 * SB_B)                 // 4608 per gate
#define STAGE_BYTES (A_BYTES + 4 * BG_BYTES)  // 23552
#define NSTAGES   4
#define SS        260                         // epilogue staging stride (floats)
#define SMEM_BYTES (NSTAGES * STAGE_BYTES)    // 94208/CTA; 2 CTAs/SM fits

__device__ static __half A_h[(size_t)BATCH * 2048];      // combined [x|h], 32MB
__device__ static __half W_h[4][(size_t)2048 * 1024];    // per-gate weights, 16MB

// ---------------------------------------------------------------- convert ---
__global__ void __launch_bounds__(256) convert_kernel(
    const float* __restrict__ x, const float* __restrict__ h,
    const float* __restrict__ Wf, const float* __restrict__ Wi,
    const float* __restrict__ Wc, const float* __restrict__ Wo)
{
    const size_t NA = (size_t)BATCH * 2048 / 4;
    const size_t NW = (size_t)2048 * 1024 / 4;
    const size_t total = NA + 4 * NW;
    const size_t stride = (size_t)gridDim.x * blockDim.x;

    for (size_t i = (size_t)blockIdx.x * blockDim.x + threadIdx.x;
         i < total; i += stride) {
        float4 v;
        __half* dst;
        if (i < NA) {
            size_t m = i >> 9;
            size_t k = (i & 511) * 4;
            const float* src = (k < 1024) ? (x + m * 1024 + k)
                                          : (h + m * 1024 + (k - 1024));
            v = *reinterpret_cast<const float4*>(src);
            dst = &A_h[i * 4];
        } else {
            size_t j = i - NA;
            size_t g = j / NW;
            size_t r = j - g * NW;
            const float* Wg = (g == 0) ? Wf : (g == 1) ? Wi : (g == 2) ? Wc : Wo;
            v = *reinterpret_cast<const float4*>(Wg + r * 4);
            dst = &W_h[g][r * 4];
        }
        __half2 lo = __floats2half2_rn(v.x, v.y);
        __half2 hi = __floats2half2_rn(v.z, v.w);
        uint2 out = { *reinterpret_cast<uint32_t*>(&lo), *reinterpret_cast<uint32_t*>(&hi) };
        *reinterpret_cast<uint2*>(dst) = out;
    }
}

// ------------------------------------------------------------------ GEMM ----
__device__ __forceinline__ uint32_t s2u(const void* p) {
    uint32_t a;
    asm("{ .reg .u64 t; cvta.to.shared.u64 t, %1; cvt.u32.u64 %0, t; }"
        : "=r"(a) : "l"(p));
    return a;
}
__device__ __forceinline__ void cp16(uint32_t dst, const __half* src) {
    asm volatile("cp.async.cg.shared.global [%0], [%1], 16;" :: "r"(dst), "l"(src));
}
#define CP_COMMIT() asm volatile("cp.async.commit_group;" ::: "memory")
#define CP_WAIT(n)  asm volatile("cp.async.wait_group %0;" :: "n"(n) : "memory")

__device__ __forceinline__ void ldsm4(uint32_t* r, uint32_t addr) {
    asm volatile("ldmatrix.sync.aligned.m8n8.x4.shared.b16 {%0,%1,%2,%3}, [%4];"
                 : "=r"(r[0]), "=r"(r[1]), "=r"(r[2]), "=r"(r[3]) : "r"(addr));
}
__device__ __forceinline__ void ldsm4t(uint32_t* r, uint32_t addr) {
    asm volatile("ldmatrix.sync.aligned.m8n8.x4.trans.shared.b16 {%0,%1,%2,%3}, [%4];"
                 : "=r"(r[0]), "=r"(r[1]), "=r"(r[2]), "=r"(r[3]) : "r"(addr));
}
__device__ __forceinline__ void mma16(float* d, const uint32_t* a, const uint32_t* b) {
    asm volatile(
        "mma.sync.aligned.m16n8k16.row.col.f32.f16.f16.f32 "
        "{%0,%1,%2,%3}, {%4,%5,%6,%7}, {%8,%9}, {%0,%1,%2,%3};"
        : "+f"(d[0]), "+f"(d[1]), "+f"(d[2]), "+f"(d[3])
        : "r"(a[0]), "r"(a[1]), "r"(a[2]), "r"(a[3]), "r"(b[0]), "r"(b[1]));
}
__device__ __forceinline__ float sigf(float v) {
    return __fdividef(1.0f, 1.0f + __expf(-v));
}
__device__ __forceinline__ float tanhf_e(float v) {
    float ax = fabsf(v);
    float e = __expf(-2.0f * ax);
    float t = __fdividef(1.0f - e, 1.0f + e);
    return copysignf(t, v);
}

// cp.async one BK=32 stage, 128 threads:
// A: 256 chunks (2/thread), B: 1024 chunks (8/thread, gate = c>>1)
__device__ __forceinline__ void load_stage(int T, int tid, uint32_t sb, int m0, int n0)
{
    const uint32_t Ab = sb + (T % NSTAGES) * STAGE_BYTES;
    const int k0 = T * 32;
    #pragma unroll
    for (int c = 0; c < 2; c++) {
        int idx = c * 128 + tid;
        int row = idx >> 2, col = idx & 3;
        cp16(Ab + row * SA_B + col * 16,
             &A_h[(size_t)(m0 + row) * 2048 + k0 + col * 8]);
    }
    const uint32_t Bb = Ab + A_BYTES;
    #pragma unroll
    for (int c = 0; c < 8; c++) {
        int g = c >> 1;
        int idx = (c & 1) * 128 + tid;
        int kr = idx >> 3, col = idx & 7;
        cp16(Bb + g * BG_BYTES + kr * SB_B + col * 16,
             &W_h[g][(size_t)(k0 + kr) * 1024 + n0 + col * 8]);
    }
}

__global__ void __launch_bounds__(128, 2)
lstm_mma(const float* __restrict__ cellp,
         const float* __restrict__ bf, const float* __restrict__ bi,
         const float* __restrict__ bc, const float* __restrict__ bo,
         float* __restrict__ outh, float* __restrict__ outc)
{
    extern __shared__ float sm[];
    const uint32_t sb = s2u(sm);

    const int tid  = threadIdx.x;
    const int lane = tid & 31;
    const int g    = tid >> 5;            // warp == gate (0..3)
    const int m0   = blockIdx.x * 64;
    const int n0   = blockIdx.y * 64;

    const int l15  = lane & 15;
    const int ahi  = (lane >> 4) * 16;    // A: 16B k-half select
    const int bhi  = (lane >> 4) * 8;     // B: n-chunk select

    float acc[4][8][4];
    #pragma unroll
    for (int mt = 0; mt < 4; mt++)
        #pragma unroll
        for (int nt = 0; nt < 8; nt++)
            #pragma unroll
            for (int j = 0; j < 4; j++) acc[mt][nt][j] = 0.0f;

    // frag ldsm helper (buf0 = ks0 frags, buf1 = ks1 frags)
    uint32_t afr[2][4][4], bfr[2][8][2];
    auto frag_load = [&](int s, int ks, int buf) {
        const uint32_t Ab = sb + s * STAGE_BYTES;
        const uint32_t Bg = Ab + A_BYTES + g * BG_BYTES;
        #pragma unroll
        for (int mt = 0; mt < 4; mt++)
            ldsm4(afr[buf][mt],
                  Ab + (uint32_t)(mt * 16 + l15) * SA_B + (uint32_t)(ks * 32 + ahi));
        #pragma unroll
        for (int np = 0; np < 4; np++) {
            uint32_t r[4];
            ldsm4t(r, Bg + (uint32_t)(ks * 16 + l15) * SB_B
                         + (uint32_t)(np * 16 + bhi) * 2);
            bfr[buf][np * 2][0] = r[0]; bfr[buf][np * 2][1] = r[1];
            bfr[buf][np * 2 + 1][0] = r[2]; bfr[buf][np * 2 + 1][1] = r[3];
        }
    };

    // prologue: stages 0,1 in flight; stage 0 published; frags(0, ks0) in regs
    load_stage(0, tid, sb, m0, n0); CP_COMMIT();
    load_stage(1, tid, sb, m0, n0); CP_COMMIT();
    CP_WAIT(1);                 // own copies of stage 0 done
    __syncthreads();            // publish stage 0
    frag_load(0, 0, 0);

    for (int t = 0; t < 64; t++) {
        const int s = t & (NSTAGES - 1);

        // stage t ks1 frags (stage t published at mid-barrier of t-1 / prologue)
        frag_load(s, 1, 1);

        // issue loads for stage t+2 (slot (t-2)%4; its readers finished
        // before mid-barrier(t-2) < mid-barrier(t-1) < this issue)
        if (t < 62) { load_stage(t + 2, tid, sb, m0, n0); CP_COMMIT(); }

        // HMMAs on buf0 (covers the wait+barrier below from the pipe's view)
        #pragma unroll
        for (int mt = 0; mt < 4; mt++)
            #pragma unroll
            for (int nt = 0; nt < 8; nt++)
                mma16(acc[mt][nt], afr[0][mt], bfr[0][nt]);

        // retire own copies of stage t+1, then publish to all threads.
        // t=62: pending={63} only, so wait(1) would be a no-op -> wait(0).
        if (t < 62) CP_WAIT(1); else CP_WAIT(0);
        __syncthreads();

        // cross-iteration preload: next stage's ks0 frags (now safe)
        if (t < 63) frag_load((t + 1) & (NSTAGES - 1), 0, 0);

        // HMMAs on buf1
        #pragma unroll
        for (int mt = 0; mt < 4; mt++)
            #pragma unroll
            for (int nt = 0; nt < 8; nt++)
                mma16(acc[mt][nt], afr[1][mt], bfr[1][nt]);
    }
    __syncthreads();       // mainloop done; smem reused for staging

    // ---- stage gate values through smem (gates live in different warps) ----
    #pragma unroll
    for (int mt = 0; mt < 4; mt++) {
        #pragma unroll
        for (int nt = 0; nt < 8; nt++) {
            int r0 = mt * 16 + (lane >> 2);
            int cb = g * 64 + nt * 8 + (lane & 3) * 2;
            *(float2*)&sm[(size_t)r0 * SS + cb]       = make_float2(acc[mt][nt][0], acc[mt][nt][1]);
            *(float2*)&sm[(size_t)(r0 + 8) * SS + cb] = make_float2(acc[mt][nt][2], acc[mt][nt][3]);
        }
    }
    __syncthreads();

    // ---- fused LSTM combine + store (64 x 64 tile, 32 elems/thread) ----
    const int nl   = tid & 63;
    const int mseg = tid >> 6;            // 0..1
    const int n    = n0 + nl;
    const float Bf = __ldg(bf + n);
    const float Bi = __ldg(bi + n);
    const float Bc = __ldg(bc + n);
    const float Bo = __ldg(bo + n);

    #pragma unroll 4
    for (int r = 0; r < 32; r++) {
        int m = r * 2 + mseg;
        const float* row = &sm[(size_t)m * SS];
        float gf = row[nl]       + Bf;
        float gi = row[64 + nl]  + Bi;
        float gc = row[128 + nl] + Bc;
        float go = row[192 + nl] + Bo;

        float F  = sigf(gf);
        float I  = sigf(gi);
        float O  = sigf(go);
        float CD = tanhf_e(gc);

        size_t gidx = (size_t)(m0 + m) * 1024 + n;
        float cold = __ldg(cellp + gidx);
        float nc = fmaf(F, cold, I * CD);
        float nh = O * tanhf_e(nc);
        outh[gidx] = nh;
        outc[gidx] = nc;
    }
}

extern "C" void kernel_launch(void* const* d_in, const int* in_sizes, int n_in,
                              void* d_out, int out_size)
{
    const float* x    = (const float*)d_in[0];   // [B, 1024]
    const float* h    = (const float*)d_in[1];   // [B, 1024]
    const float* cell = (const float*)d_in[2];   // [B, 1024]
    const float* Wf   = (const float*)d_in[3];   // [2048, 1024]
    const float* bf   = (const float*)d_in[4];
    const float* Wi   = (const float*)d_in[5];
    const float* bi   = (const float*)d_in[6];
    const float* Wc   = (const float*)d_in[7];
    const float* bc   = (const float*)d_in[8];
    const float* Wo   = (const float*)d_in[9];
    const float* bo   = (const float*)d_in[10];

    const int B = in_sizes[0] / 1024;            // 8192

    static bool attr_set = false;
    if (!attr_set) {
        cudaFuncSetAttribute(lstm_mma, cudaFuncAttributeMaxDynamicSharedMemorySize,
                             SMEM_BYTES);
        attr_set = true;
    }

    convert_kernel<<<2048, 256>>>(x, h, Wf, Wi, Wc, Wo);

    float* outh = (float*)d_out;
    float* outc = (float*)d_out + (size_t)B * 1024;

    dim3 grid(B / 64, 16);
    lstm_mma<<<grid, 128, SMEM_BYTES>>>(cell, bf, bi, bc, bo, outh, outc);
}